// round 3
// baseline (speedup 1.0000x reference)
#include <cuda_runtime.h>
#include <math.h>
#include <stdint.h>

#define BATCH 32
#define CDIM  256
#define TLEN  2048
#define NTOK  (BATCH * TLEN)   // 65536
#define KCODES 1024
#define BETA  0.25f

// ---------------- device scratch (no allocations allowed) ----------------
__device__ float        g_cnorm[KCODES];
__device__ float        g_znorm[NTOK];
__device__ int          g_idx[NTOK];
__device__ unsigned int g_counts[KCODES];
__device__ double       g_sqsum;

// ---------------- packed f32x2 helpers ----------------
__device__ __forceinline__ unsigned long long pack2(float lo, float hi) {
    unsigned long long r;
    asm("mov.b64 %0, {%1, %2};" : "=l"(r) : "f"(lo), "f"(hi));
    return r;
}
__device__ __forceinline__ void unpack2(unsigned long long p, float& lo, float& hi) {
    asm("mov.b64 {%0, %1}, %2;" : "=f"(lo), "=f"(hi) : "l"(p));
}
__device__ __forceinline__ void fma2(unsigned long long& d,
                                     unsigned long long a,
                                     unsigned long long b) {
    asm("fma.rn.f32x2 %0, %1, %2, %0;" : "+l"(d) : "l"(a), "l"(b));
}

// ---------------- kernel 0: init (cnorm fp64->fp32, zero counts/sqsum) ----------------
__global__ void vq_init_kernel(const float* __restrict__ cb) {
    int k = blockIdx.x * blockDim.x + threadIdx.x;
    if (k < KCODES) {
        const float* r = cb + (size_t)k * CDIM;
        double s = 0.0;
        #pragma unroll 8
        for (int c = 0; c < CDIM; c++) { double v = (double)r[c]; s += v * v; }
        g_cnorm[k] = (float)s;
        g_counts[k] = 0u;
    }
    if (k == 0) g_sqsum = 0.0;
}

// ---------------- kernel 0b: per-token ||z||^2 (fp64 accumulate -> fp32) ----------------
__global__ void vq_znorm_kernel(const float* __restrict__ z) {
    int n = blockIdx.x * blockDim.x + threadIdx.x;
    if (n >= NTOK) return;
    int b = n / TLEN;
    int t = n % TLEN;
    const float* p = z + (size_t)b * CDIM * TLEN + t;
    double s = 0.0;
    #pragma unroll 8
    for (int c = 0; c < CDIM; c++) {
        double v = (double)p[(size_t)c * TLEN];
        s += v * v;
    }
    g_znorm[n] = (float)s;
}

// ---------------- kernel 1: argmin GEMM ----------------
// Reference: d[n,k] = fl(fl(znorm_n + cnorm_k) - 2*dot_nk), argmin (first index wins).
// We replicate the exact fp32 rounding structure of the epilogue.
#define TM 128
#define TN 128
#define KC 16

__global__ __launch_bounds__(256, 1)
void vq_argmin_kernel(const float* __restrict__ z, const float* __restrict__ cb) {
    __shared__ float sA[KC][TM];        // [c][token]
    __shared__ float sB[KC][TN];        // [c][code]
    __shared__ float sCN[TN];
    __shared__ float sZN[TM];
    __shared__ float red_d[TM][17];
    __shared__ int   red_k[TM][17];

    const int tid = threadIdx.x;
    const int tx = tid & 15;
    const int ty = tid >> 4;

    const int tok0 = blockIdx.x * TM;
    const int b    = tok0 / TLEN;
    const int t0   = tok0 % TLEN;
    const float* zb = z + (size_t)b * CDIM * TLEN + t0;

    if (tid < TM) sZN[tid] = g_znorm[tok0 + tid];
    __syncthreads();

    float zn[8];
    #pragma unroll
    for (int i = 0; i < 8; i++) {
        int tok = (i < 4) ? (ty * 4 + i) : (64 + ty * 4 + (i - 4));
        zn[i] = sZN[tok];
    }

    float bd[8];
    int   bk[8];
    #pragma unroll
    for (int i = 0; i < 8; i++) { bd[i] = 3.4e38f; bk[i] = 0; }

    for (int kt = 0; kt < KCODES; kt += TN) {
        __syncthreads();                      // protect sCN / smem reuse
        if (tid < TN) sCN[tid] = g_cnorm[kt + tid];

        unsigned long long accp[8][4];
        #pragma unroll
        for (int i = 0; i < 8; i++)
            #pragma unroll
            for (int j = 0; j < 4; j++) accp[i][j] = 0ULL;

        for (int c0 = 0; c0 < CDIM; c0 += KC) {
            __syncthreads();
            // load z tile: 16 features x 128 tokens (coalesced: tokens contiguous)
            {
                int cc = tid >> 4, lane = tid & 15;
                const float4* src = (const float4*)(zb + (size_t)(c0 + cc) * TLEN);
                float4 v0 = src[lane];
                float4 v1 = src[lane + 16];
                *(float4*)&sA[cc][lane * 4]      = v0;
                *(float4*)&sA[cc][64 + lane * 4] = v1;
            }
            // load codebook tile: 128 codes x 16 features, transposed into sB[c][k]
            {
                #pragma unroll
                for (int r = 0; r < 2; r++) {
                    int q  = tid + r * 256;
                    int k  = q & 127;
                    int cq = q >> 7;          // 0..3
                    float4 v = *(const float4*)(cb + (size_t)(kt + k) * CDIM + c0 + cq * 4);
                    sB[cq * 4 + 0][k] = v.x;
                    sB[cq * 4 + 1][k] = v.y;
                    sB[cq * 4 + 2][k] = v.z;
                    sB[cq * 4 + 3][k] = v.w;
                }
            }
            __syncthreads();

            #pragma unroll
            for (int cc = 0; cc < KC; cc++) {
                float4 a0 = *(float4*)&sA[cc][ty * 4];
                float4 a1 = *(float4*)&sA[cc][64 + ty * 4];
                float4 b0 = *(float4*)&sB[cc][tx * 4];
                float4 b1 = *(float4*)&sB[cc][64 + tx * 4];
                float av[8] = {a0.x, a0.y, a0.z, a0.w, a1.x, a1.y, a1.z, a1.w};
                float bv[8] = {b0.x, b0.y, b0.z, b0.w, b1.x, b1.y, b1.z, b1.w};
                unsigned long long ap[8], bp[4];
                #pragma unroll
                for (int i = 0; i < 8; i++) ap[i] = pack2(av[i], av[i]);
                #pragma unroll
                for (int j = 0; j < 4; j++) bp[j] = pack2(bv[2 * j], bv[2 * j + 1]);
                #pragma unroll
                for (int i = 0; i < 8; i++)
                    #pragma unroll
                    for (int j = 0; j < 4; j++)
                        fma2(accp[i][j], ap[i], bp[j]);
            }
        }

        // epilogue: replicate reference rounding d = rn(rn(zn + cn) - 2*dot)
        // candidates enumerated in ascending k; strict '<' keeps first (lowest) index
        #pragma unroll
        for (int i = 0; i < 8; i++) {
            #pragma unroll
            for (int j = 0; j < 4; j++) {
                float lo, hi;
                unpack2(accp[i][j], lo, hi);
                int m0 = 2 * j;
                int col0 = (m0 < 4) ? (tx * 4 + m0) : (64 + tx * 4 + (m0 - 4));
                int col1 = col0 + 1;
                float t0a = __fadd_rn(zn[i], sCN[col0]);
                float t1a = __fadd_rn(zn[i], sCN[col1]);
                float d0 = __fadd_rn(t0a, __fmul_rn(-2.0f, lo));
                float d1 = __fadd_rn(t1a, __fmul_rn(-2.0f, hi));
                if (d0 < bd[i]) { bd[i] = d0; bk[i] = kt + col0; }
                if (d1 < bd[i]) { bd[i] = d1; bk[i] = kt + col1; }
            }
        }
    }

    // cross-thread (tx) reduction per token, lowest-index tie-break
    __syncthreads();
    #pragma unroll
    for (int i = 0; i < 8; i++) {
        int tok = (i < 4) ? (ty * 4 + i) : (64 + ty * 4 + (i - 4));
        red_d[tok][tx] = bd[i];
        red_k[tok][tx] = bk[i];
    }
    __syncthreads();
    if (tid < TM) {
        float best = red_d[tid][0];
        int bestk  = red_k[tid][0];
        #pragma unroll
        for (int x = 1; x < 16; x++) {
            float d = red_d[tid][x];
            int   k = red_k[tid][x];
            if (d < best || (d == best && k < bestk)) { best = d; bestk = k; }
        }
        g_idx[tok0 + tid] = bestk;
    }
}

// ---------------- kernel 2: z_q gather + loss partial ----------------
__global__ void vq_zq_kernel(const float* __restrict__ z,
                             const float* __restrict__ cb,
                             float* __restrict__ zq_out) {
    const int b = blockIdx.x >> 8;        // /256
    const int c = blockIdx.x & 255;
    const float* zr  = z      + ((size_t)b * CDIM + c) * TLEN;
    float*       orow = zq_out + ((size_t)b * CDIM + c) * TLEN;
    const int*   idxr = g_idx + (size_t)b * TLEN;

    float s = 0.f;
    for (int t = threadIdx.x; t < TLEN; t += blockDim.x) {
        int k = idxr[t];
        float q = cb[(size_t)k * CDIM + c];
        float d = q - zr[t];
        s += d * d;
        orow[t] = q;
    }
    #pragma unroll
    for (int o = 16; o; o >>= 1) s += __shfl_down_sync(0xffffffffu, s, o);
    __shared__ float ws[8];
    if ((threadIdx.x & 31) == 0) ws[threadIdx.x >> 5] = s;
    __syncthreads();
    if (threadIdx.x == 0) {
        float tot = 0.f;
        #pragma unroll
        for (int w = 0; w < 8; w++) tot += ws[w];
        atomicAdd(&g_sqsum, (double)tot);
    }
}

// ---------------- kernel 3: one-hot scatter + counts + index output ----------------
__global__ void vq_scatter_kernel(float* __restrict__ onehot,
                                  float* __restrict__ idx_out) {
    int n = blockIdx.x * blockDim.x + threadIdx.x;
    if (n >= NTOK) return;
    int k = g_idx[n];
    onehot[(size_t)n * KCODES + k] = 1.0f;
    atomicAdd(&g_counts[k], 1u);
    idx_out[n] = (float)k;
}

// ---------------- kernel 4: finalize loss + perplexity ----------------
__global__ void vq_finalize_kernel(float* __restrict__ loss_out,
                                   float* __restrict__ perp_out) {
    const int tid = threadIdx.x;
    double local = 0.0;
    for (int k = tid; k < KCODES; k += 256) {
        float p = (float)g_counts[k] * (1.0f / (float)NTOK);
        local += (double)(p * logf(p + 1e-10f));
    }
    __shared__ double sh[256];
    sh[tid] = local;
    __syncthreads();
    for (int o = 128; o; o >>= 1) {
        if (tid < o) sh[tid] += sh[tid + o];
        __syncthreads();
    }
    if (tid == 0) {
        perp_out[0] = expf(-(float)sh[0]);
        loss_out[0] = (1.0f + BETA) *
                      (float)(g_sqsum / (double)((size_t)NTOK * CDIM));
    }
}

// ---------------- launch ----------------
extern "C" void kernel_launch(void* const* d_in, const int* in_sizes, int n_in,
                              void* d_out, int out_size) {
    const float* z  = (const float*)d_in[0];
    const float* cb = (const float*)d_in[1];
    float* out = (float*)d_out;

    // output layout: loss | z_q_out (B*C*T) | perplexity | one-hot (N*K) | indices (N)
    const size_t n_zq = (size_t)BATCH * CDIM * TLEN;   // 16777216
    float* loss_out = out;
    float* zq_out   = out + 1;
    float* perp_out = out + 1 + n_zq;
    float* onehot   = perp_out + 1;
    float* idx_out  = onehot + (size_t)NTOK * KCODES;

    cudaMemsetAsync(onehot, 0, (size_t)NTOK * KCODES * sizeof(float), 0);

    vq_init_kernel<<<8, 128>>>(cb);
    vq_znorm_kernel<<<NTOK / 256, 256>>>(z);
    vq_argmin_kernel<<<NTOK / TM, 256>>>(z, cb);
    vq_zq_kernel<<<BATCH * CDIM, 256>>>(z, cb, zq_out);
    vq_scatter_kernel<<<NTOK / 256, 256>>>(onehot, idx_out);
    vq_finalize_kernel<<<1, 256>>>(loss_out, perp_out);
}